// round 17
// baseline (speedup 1.0000x reference)
#include <cuda_runtime.h>
#include <cuda_fp16.h>
#include <cstdint>

// ---------------------------------------------------------------------------
// Sparse 3D CNN pipeline. Round 17: persistent-B conv (B panel loaded once
// per CTA, x-tiles looped; halves mainloop cp.async ops), exact tail-wait
// counts, BN-apply fused into both pools. CSR pool1 / fused pool2+global /
// parallel counts / fused weight convert retained from round 16.
// ---------------------------------------------------------------------------

__device__ float  g_acc[32768 * 512];
__device__ __half g_hA[32768 * 512];
__device__ __half g_hB[32768 * 512];
__device__ __half g_wh[38928384];               // fp16 weights [27][512][ci]
__device__ float  g_sum[512];
__device__ float  g_sumsq[512];
__device__ float  g_coefA[512];
__device__ float  g_coefB[512];
__device__ int    g_cnt1[27];
__device__ int    g_cnt2[27];
__device__ int    g_done;
__device__ int    g_seg1[32770];
__device__ int    g_ptr1[32768];
__device__ int    g_inv1[32768];
__device__ float  g_glob[8 * 512];
__device__ float  g_fcb1[8 * 4096];
__device__ float  g_fcb2[8 * 4096];

#define BM 128
#define BN 128
#define BK 32
#define ALDH 40
#define A_ST_H (BM * ALDH)
// dynamic smem: B panel 128*(K+8) halves, then 4 A stages, then rs/os ints
#define SMEM_FOR(K) ((128 * ((K) + 8) + 4 * A_ST_H) * 2 + 2 * BM * 4)
#define SMEM_MAX SMEM_FOR(512)

static __device__ __forceinline__ uint32_t smem_u32(const void* p) {
    uint32_t a;
    asm("{ .reg .u64 t; cvta.to.shared.u64 t, %1; cvt.u32.u64 %0, t; }"
        : "=r"(a) : "l"(p));
    return a;
}
static __device__ __forceinline__ void cp16(uint32_t dst, const void* src, bool v) {
    asm volatile("cp.async.cg.shared.global [%0], [%1], 16, %2;"
                 :: "r"(dst), "l"(src), "r"(v ? 16 : 0));
}
static __device__ __forceinline__ void cp16ca(uint32_t dst, const void* src) {
    asm volatile("cp.async.ca.shared.global [%0], [%1], 16;"
                 :: "r"(dst), "l"(src));
}
#define CP_COMMIT() asm volatile("cp.async.commit_group;" ::: "memory")
static __device__ __forceinline__ void cp_waitN(int n) {
    if (n >= 2)      asm volatile("cp.async.wait_group 2;" ::: "memory");
    else if (n == 1) asm volatile("cp.async.wait_group 1;" ::: "memory");
    else             asm volatile("cp.async.wait_group 0;" ::: "memory");
}
static __device__ __forceinline__ void ldsm4(uint32_t& r0, uint32_t& r1,
                                             uint32_t& r2, uint32_t& r3,
                                             uint32_t addr) {
    asm volatile("ldmatrix.sync.aligned.m8n8.x4.shared.b16 {%0,%1,%2,%3}, [%4];"
                 : "=r"(r0), "=r"(r1), "=r"(r2), "=r"(r3) : "r"(addr));
}
static __device__ __forceinline__ void red4(float* p, float v0, float v1,
                                            float v2, float v3) {
    asm volatile("red.global.add.v4.f32 [%0], {%1,%2,%3,%4};"
                 :: "l"(p), "f"(v0), "f"(v1), "f"(v2), "f"(v3) : "memory");
}

// mainloop body over one staged A tile vs persistent B panel
#define TILE_MMA_PB(Af, Bs_u, BL, kit)                                         \
    do {                                                                       \
        _Pragma("unroll")                                                      \
        for (int h = 0; h < 2; h++) {                                          \
            int kb = h * 16;                                                   \
            int kglob = (kit) * BK + kb + (lg >> 1) * 8;                       \
            uint32_t a[4][4];                                                  \
            _Pragma("unroll")                                                  \
            for (int mt = 0; mt < 4; mt++) {                                   \
                int rowa = wm * 64 + mt * 16 + lr8 + (lg & 1) * 8;             \
                ldsm4(a[mt][0], a[mt][1], a[mt][2], a[mt][3],                  \
                      (Af) + ((rowa * ALDH) + kb + (lg >> 1) * 8) * 2);        \
            }                                                                  \
            uint32_t b[4][2];                                                  \
            _Pragma("unroll")                                                  \
            for (int np = 0; np < 2; np++) {                                   \
                int rowb = wn * 32 + np * 16 + lr8 + (lg & 1) * 8;             \
                uint32_t r0, r1, r2, r3;                                       \
                ldsm4(r0, r1, r2, r3, (Bs_u) + ((long)rowb * (BL) + kglob) * 2);\
                b[np * 2 + 0][0] = r0; b[np * 2 + 0][1] = r2;                  \
                b[np * 2 + 1][0] = r1; b[np * 2 + 1][1] = r3;                  \
            }                                                                  \
            _Pragma("unroll")                                                  \
            for (int mt = 0; mt < 4; mt++)                                     \
                _Pragma("unroll")                                              \
                for (int nt = 0; nt < 4; nt++) {                               \
                    asm volatile(                                              \
                        "mma.sync.aligned.m16n8k16.row.col.f32.f16.f16.f32 "   \
                        "{%0,%1,%2,%3}, {%4,%5,%6,%7}, {%8,%9}, {%0,%1,%2,%3};"\
                        : "+f"(acc[mt][nt][0]), "+f"(acc[mt][nt][1]),          \
                          "+f"(acc[mt][nt][2]), "+f"(acc[mt][nt][3])           \
                        : "r"(a[mt][0]), "r"(a[mt][1]), "r"(a[mt][2]),         \
                          "r"(a[mt][3]), "r"(b[nt][0]), "r"(b[nt][1]));        \
                }                                                              \
        }                                                                      \
    } while (0)

// ---- parallel map-pair counting ----
__global__ void k_count_par(const int* __restrict__ out_idx, int P, int sentinel,
                            int* __restrict__ counts) {
    int k = blockIdx.x;
    const int* o = out_idx + (long)k * P;
    int chunk = (P + gridDim.y - 1) / gridDim.y;
    int lo = blockIdx.y * chunk;
    int hi = min(lo + chunk, P);
    int c = 0;
    for (int p = lo + threadIdx.x; p < hi; p += blockDim.x) c += (o[p] != sentinel);
    __shared__ int sm[256];
    sm[threadIdx.x] = c;
    __syncthreads();
    for (int s = 128; s > 0; s >>= 1) {
        if (threadIdx.x < s) sm[threadIdx.x] += sm[threadIdx.x + s];
        __syncthreads();
    }
    if (threadIdx.x == 0) atomicAdd(&counts[k], sm[0]);
}

// ---- pool1 CSR build ----
__global__ void k_hist(const int* __restrict__ idx, int n, int* __restrict__ segp1) {
    int i = blockIdx.x * blockDim.x + threadIdx.x;
    int stride = gridDim.x * blockDim.x;
    for (; i < n; i += stride) atomicAdd(&segp1[idx[i] + 1], 1);
}

__global__ void k_scan(int* __restrict__ a, int m, int* __restrict__ ptr) {
    __shared__ int sm[1024];
    __shared__ int carry;
    if (threadIdx.x == 0) carry = 0;
    __syncthreads();
    for (int base = 0; base < m; base += 1024) {
        int i = base + threadIdx.x;
        int v = (i < m) ? a[i] : 0;
        sm[threadIdx.x] = v;
        __syncthreads();
        for (int off = 1; off < 1024; off <<= 1) {
            int t = (threadIdx.x >= off) ? sm[threadIdx.x - off] : 0;
            __syncthreads();
            sm[threadIdx.x] += t;
            __syncthreads();
        }
        int val = sm[threadIdx.x] + carry;
        if (i < m) {
            a[i] = val;
            if (i < m - 1) ptr[i] = val;
        }
        __syncthreads();
        if (threadIdx.x == 0) carry += sm[1023];
        __syncthreads();
    }
}

__global__ void k_scatter(const int* __restrict__ idx, int n,
                          int* __restrict__ ptr, int* __restrict__ inv) {
    int i = blockIdx.x * blockDim.x + threadIdx.x;
    int stride = gridDim.x * blockDim.x;
    for (; i < n; i += stride) {
        int s = atomicAdd(&ptr[idx[i]], 1);
        inv[s] = i;
    }
}

// pool1 with fused BN-apply+ReLU: reads f32 acc, writes half
__global__ void k_pool_csr_bn(const float* __restrict__ x, const int* __restrict__ seg,
                              const int* __restrict__ inv, __half* __restrict__ y) {
    int sid = blockIdx.x;
    int s0 = seg[sid], s1 = seg[sid + 1];
    for (int c = threadIdx.x; c < 512; c += blockDim.x) {
        float a = g_coefA[c], b = g_coefB[c];
        float m = 0.f;
        for (int j = s0; j < s1; j++) {
            float v = fmaxf(x[(long)inv[j] * 512 + c] * a + b, 0.f);
            m = fmaxf(m, v);
        }
        y[(long)sid * 512 + c] = __float2half(m);
    }
}

// fused pool2+global with BN-apply+ReLU: reads f32 acc
__global__ void k_pool_compose_bn(const float* __restrict__ x,
                                  const int* __restrict__ p2,
                                  const int* __restrict__ bidx,
                                  float* __restrict__ glob, int n2) {
    long total = (long)n2 * 512;
    long i = (long)blockIdx.x * blockDim.x + threadIdx.x;
    long stride = (long)gridDim.x * blockDim.x;
    for (; i < total; i += stride) {
        int r = (int)(i >> 9);
        int c = (int)(i & 511);
        int b = bidx[p2[r]];
        float v = fmaxf(x[i] * g_coefA[c] + g_coefB[c], 0.f);
        atomicMax((int*)&glob[(long)b * 512 + c], __float_as_int(v));
    }
}

// Single-layer convert: W[27][ci][512] f32 -> Wh[27][512][ci] half.
__global__ void k_wt(const float* __restrict__ W, __half* __restrict__ out, int ci) {
    __shared__ float t[32][33];
    int k = blockIdx.z;
    int i0 = blockIdx.y * 32, o0 = blockIdx.x * 32;
    int tx = threadIdx.x, ty = threadIdx.y;
#pragma unroll
    for (int r = 0; r < 32; r += 8)
        t[ty + r][tx] = W[((long)k * ci + i0 + ty + r) * 512 + o0 + tx];
    __syncthreads();
#pragma unroll
    for (int r = 0; r < 32; r += 8)
        out[((long)k * 512 + o0 + ty + r) * ci + i0 + tx] = __float2half(t[tx][ty + r]);
}

__global__ void k_wt5(const float* w1, const float* w2, const float* w3,
                      const float* w4, const float* w5,
                      __half* __restrict__ out0, long stride) {
    __shared__ float t[32][33];
    int layer = blockIdx.z / 27;
    int k = blockIdx.z % 27;
    const float* W = (layer == 0) ? w1 : (layer == 1) ? w2 : (layer == 2) ? w3
                   : (layer == 3) ? w4 : w5;
    __half* out = out0 + (long)layer * stride;
    int i0 = blockIdx.y * 32, o0 = blockIdx.x * 32;
    int tx = threadIdx.x, ty = threadIdx.y;
#pragma unroll
    for (int r = 0; r < 32; r += 8)
        t[ty + r][tx] = W[((long)k * 512 + i0 + ty + r) * 512 + o0 + tx];
    __syncthreads();
#pragma unroll
    for (int r = 0; r < 32; r += 8)
        out[((long)k * 512 + o0 + ty + r) * 512 + i0 + tx] = __float2half(t[tx][ty + r]);
}

__global__ void k_f2h(const float* __restrict__ x, __half* __restrict__ y, int n) {
    int i = blockIdx.x * blockDim.x + threadIdx.x;
    int stride = gridDim.x * blockDim.x;
    for (; i < n; i += stride) y[i] = __float2half(x[i]);
}

// ---------------------------------------------------------------------------
// Persistent-B gather conv: grid (xc, 4, 26). B panel loaded once per CTA,
// x-tiles looped. v4 red scatter.
// ---------------------------------------------------------------------------
__global__ __launch_bounds__(256, 2)
void k_conv_off(const __half* __restrict__ x, const __half* __restrict__ Wh,
                const int* __restrict__ in_idx, const int* __restrict__ out_idx,
                const int* __restrict__ counts, int P, int K, int skip13,
                float* __restrict__ out) {
    int koff = blockIdx.z;
    if (skip13 && koff >= 13) koff++;
    int count = counts[koff];
    if (count == 0) return;
    int col0 = blockIdx.y * BN;
    const __half* Wk = Wh + (long)koff * 512 * K;

    extern __shared__ __half smh[];
    int BL = K + 8;
    uint32_t Bs_u = smem_u32(smh);
    uint32_t As_u = Bs_u + 128 * BL * 2;
    int* rs = (int*)(smh + 128 * BL + 4 * A_ST_H);
    int* os = rs + BM;

    int tid = threadIdx.x;
    int warp = tid >> 5, lane = tid & 31;
    int wm = warp & 1, wn = warp >> 1;
    int lg = lane >> 3, lr8 = lane & 7;
    int lrow = tid >> 1;
    int lseg = (tid & 1) * 16;
    int nIter = K / BK;

    // ---- B panel preload (one group) ----
    {
        int nseg = K >> 3;
        for (int i = tid; i < 128 * nseg; i += 256) {
            int col = i / nseg, sg = i - col * nseg;
            cp16ca(Bs_u + ((long)col * BL + sg * 8) * 2,
                   Wk + (long)(col0 + col) * K + sg * 8);
        }
        CP_COMMIT();
    }

    for (int t = blockIdx.x; t * BM < count; t += gridDim.x) {
        int row0 = t * BM;
        __syncthreads();                      // protect rs/os from prior epilogue
        if (tid < BM) {
            int p = row0 + tid;
            bool v = p < count;
            rs[tid] = v ? in_idx[(long)koff * P + p] : -1;
            os[tid] = v ? out_idx[(long)koff * P + p] : -1;
        }
        __syncthreads();

        int ar = rs[lrow];
        const __half* xrow = (ar >= 0) ? &x[(long)ar * K] : nullptr;

        auto issue_stage = [&](int stage, int k0) {
            uint32_t Ab = As_u + stage * A_ST_H * 2;
            const __half* asrc = xrow ? (xrow + k0 + lseg) : x;
            cp16(Ab + (lrow * ALDH + lseg) * 2,     asrc,     xrow != nullptr);
            cp16(Ab + (lrow * ALDH + lseg + 8) * 2, asrc + 8, xrow != nullptr);
            CP_COMMIT();
        };

        float acc[4][4][4];
#pragma unroll
        for (int mt = 0; mt < 4; mt++)
#pragma unroll
            for (int nt = 0; nt < 4; nt++)
#pragma unroll
                for (int i = 0; i < 4; i++) acc[mt][nt][i] = 0.0f;

        issue_stage(0, 0);
        issue_stage(1, BK);
        issue_stage(2, 2 * BK);

        for (int it = 0; it < nIter; it++) {
            cp_waitN(nIter - 1 - it);         // min(2, remaining) semantics
            __syncthreads();
            if (it + 3 < nIter) issue_stage((it + 3) & 3, (it + 3) * BK);

            uint32_t Af = As_u + (it & 3) * A_ST_H * 2;
            TILE_MMA_PB(Af, Bs_u, BL, it);
        }

        int lr = lane >> 2, lq = lane & 3;
        int odd = lane & 1;
#pragma unroll
        for (int mt = 0; mt < 4; mt++) {
            int rbase = wm * 64 + mt * 16 + lr;
            int o_lo = os[rbase];
            int o_hi = os[rbase + 8];
            int o = odd ? o_hi : o_lo;
#pragma unroll
            for (int nt = 0; nt < 4; nt++) {
                float e0 = __shfl_xor_sync(0xffffffffu, acc[mt][nt][0], 1);
                float e1 = __shfl_xor_sync(0xffffffffu, acc[mt][nt][1], 1);
                float e2 = __shfl_xor_sync(0xffffffffu, acc[mt][nt][2], 1);
                float e3 = __shfl_xor_sync(0xffffffffu, acc[mt][nt][3], 1);
                float v0, v1, v2, v3;
                if (!odd) { v0 = acc[mt][nt][0]; v1 = acc[mt][nt][1]; v2 = e0; v3 = e1; }
                else      { v0 = e2; v1 = e3; v2 = acc[mt][nt][2]; v3 = acc[mt][nt][3]; }
                int cb = col0 + wn * 32 + nt * 8 + (lq & 2) * 2;
                if (o >= 0) red4(&out[(long)o * 512 + cb], v0, v1, v2, v3);
            }
        }
    }
}

// ---------------------------------------------------------------------------
// Persistent-B center conv: identity map, dense rows, v4 stores, initializes.
// grid (xc, 4).
// ---------------------------------------------------------------------------
__global__ __launch_bounds__(256, 2)
void k_conv_center(const __half* __restrict__ x, const __half* __restrict__ W13,
                   int n, int K, float* __restrict__ out) {
    int col0 = blockIdx.y * BN;

    extern __shared__ __half smh[];
    int BL = K + 8;
    uint32_t Bs_u = smem_u32(smh);
    uint32_t As_u = Bs_u + 128 * BL * 2;

    int tid = threadIdx.x;
    int warp = tid >> 5, lane = tid & 31;
    int wm = warp & 1, wn = warp >> 1;
    int lg = lane >> 3, lr8 = lane & 7;
    int lrow = tid >> 1;
    int lseg = (tid & 1) * 16;
    int nIter = K / BK;
    int nTiles = (n + BM - 1) / BM;

    {
        int nseg = K >> 3;
        for (int i = tid; i < 128 * nseg; i += 256) {
            int col = i / nseg, sg = i - col * nseg;
            cp16ca(Bs_u + ((long)col * BL + sg * 8) * 2,
                   W13 + (long)(col0 + col) * K + sg * 8);
        }
        CP_COMMIT();
    }

    for (int t = blockIdx.x; t < nTiles; t += gridDim.x) {
        int row0 = t * BM;
        int grow = row0 + lrow;
        const __half* xrow = (grow < n) ? &x[(long)grow * K] : nullptr;

        auto issue_stage = [&](int stage, int k0) {
            uint32_t Ab = As_u + stage * A_ST_H * 2;
            const __half* asrc = xrow ? (xrow + k0 + lseg) : x;
            cp16(Ab + (lrow * ALDH + lseg) * 2,     asrc,     xrow != nullptr);
            cp16(Ab + (lrow * ALDH + lseg + 8) * 2, asrc + 8, xrow != nullptr);
            CP_COMMIT();
        };

        float acc[4][4][4];
#pragma unroll
        for (int mt = 0; mt < 4; mt++)
#pragma unroll
            for (int nt = 0; nt < 4; nt++)
#pragma unroll
                for (int i = 0; i < 4; i++) acc[mt][nt][i] = 0.0f;

        issue_stage(0, 0);
        issue_stage(1, BK);
        issue_stage(2, 2 * BK);

        for (int it = 0; it < nIter; it++) {
            cp_waitN(nIter - 1 - it);
            __syncthreads();
            if (it + 3 < nIter) issue_stage((it + 3) & 3, (it + 3) * BK);

            uint32_t Af = As_u + (it & 3) * A_ST_H * 2;
            TILE_MMA_PB(Af, Bs_u, BL, it);
        }

        int lr = lane >> 2, lq = lane & 3;
        int odd = lane & 1;
#pragma unroll
        for (int mt = 0; mt < 4; mt++) {
            int r_lo = row0 + wm * 64 + mt * 16 + lr;
            int r = odd ? (r_lo + 8) : r_lo;
#pragma unroll
            for (int nt = 0; nt < 4; nt++) {
                float e0 = __shfl_xor_sync(0xffffffffu, acc[mt][nt][0], 1);
                float e1 = __shfl_xor_sync(0xffffffffu, acc[mt][nt][1], 1);
                float e2 = __shfl_xor_sync(0xffffffffu, acc[mt][nt][2], 1);
                float e3 = __shfl_xor_sync(0xffffffffu, acc[mt][nt][3], 1);
                float4 v;
                if (!odd) { v.x = acc[mt][nt][0]; v.y = acc[mt][nt][1]; v.z = e0; v.w = e1; }
                else      { v.x = e2; v.y = e3; v.z = acc[mt][nt][2]; v.w = acc[mt][nt][3]; }
                int cb = col0 + wn * 32 + nt * 8 + (lq & 2) * 2;
                if (r < n) *(float4*)&out[(long)r * 512 + cb] = v;
            }
        }
        __syncthreads();   // A stages drained (wait 0 at last iter); safe reuse
    }
}

// ---------------------------------------------------------------------------
// BN stats + (last block) coef. Self-resetting.
// ---------------------------------------------------------------------------
__global__ void k_bn_stats(const float* __restrict__ x, int n,
                           const float* __restrict__ gamma,
                           const float* __restrict__ beta, float inv_n) {
    int c = threadIdx.x;
    int r0 = blockIdx.x * 128;
    int rend = min(r0 + 128, n);
    float s0 = 0.f, s20 = 0.f, s1 = 0.f, s21 = 0.f;
    for (int r = r0; r < rend; r++) {
        float v0 = x[(long)r * 512 + c];
        float v1 = x[(long)r * 512 + c + 256];
        s0 += v0; s20 += v0 * v0;
        s1 += v1; s21 += v1 * v1;
    }
    atomicAdd(&g_sum[c], s0);
    atomicAdd(&g_sumsq[c], s20);
    atomicAdd(&g_sum[c + 256], s1);
    atomicAdd(&g_sumsq[c + 256], s21);

    __threadfence();
    __shared__ int is_last;
    if (threadIdx.x == 0)
        is_last = (atomicAdd(&g_done, 1) == (int)gridDim.x - 1);
    __syncthreads();
    if (is_last) {
        __threadfence();
#pragma unroll
        for (int half = 0; half < 2; half++) {
            int ch = c + half * 256;
            float mu = g_sum[ch] * inv_n;
            float var = g_sumsq[ch] * inv_n - mu * mu;
            float a = gamma[ch] * rsqrtf(var + 1e-5f);
            g_coefA[ch] = a;
            g_coefB[ch] = beta[ch] - mu * a;
            g_sum[ch] = 0.0f;
            g_sumsq[ch] = 0.0f;
        }
        if (threadIdx.x == 0) g_done = 0;
    }
}

__global__ void k_bn_apply_h(const float* __restrict__ x, __half* __restrict__ y,
                             int total8) {
    int i = blockIdx.x * blockDim.x + threadIdx.x;
    int stride = gridDim.x * blockDim.x;
    for (; i < total8; i += stride) {
        float4 v0 = ((const float4*)x)[i * 2];
        float4 v1 = ((const float4*)x)[i * 2 + 1];
        int c = (i * 8) & 511;
        float4 a0 = *(const float4*)&g_coefA[c];
        float4 a1 = *(const float4*)&g_coefA[c + 4];
        float4 b0 = *(const float4*)&g_coefB[c];
        float4 b1 = *(const float4*)&g_coefB[c + 4];
        __half2 h[4];
        h[0] = __floats2half2_rn(fmaxf(v0.x * a0.x + b0.x, 0.f), fmaxf(v0.y * a0.y + b0.y, 0.f));
        h[1] = __floats2half2_rn(fmaxf(v0.z * a0.z + b0.z, 0.f), fmaxf(v0.w * a0.w + b0.w, 0.f));
        h[2] = __floats2half2_rn(fmaxf(v1.x * a1.x + b1.x, 0.f), fmaxf(v1.y * a1.y + b1.y, 0.f));
        h[3] = __floats2half2_rn(fmaxf(v1.z * a1.z + b1.z, 0.f), fmaxf(v1.w * a1.w + b1.w, 0.f));
        ((uint4*)y)[i] = *(const uint4*)h;
    }
}

// ---------------------------------------------------------------------------
__global__ __launch_bounds__(256)
void k_fc(const float* __restrict__ x, const float* __restrict__ w,
          const float* __restrict__ bias, float* __restrict__ y,
          int K, int N, int do_relu) {
    __shared__ float xs[8 * 512];
    __shared__ float red_[8][32][8];
    int tid = threadIdx.x;
    int cj = tid & 31, s = tid >> 5;
    int j = blockIdx.x * 32 + cj;
    bool jv = j < N;

    float acc[8];
#pragma unroll
    for (int b = 0; b < 8; b++) acc[b] = 0.f;

    for (int k0 = 0; k0 < K; k0 += 512) {
        for (int i = tid; i < 8 * 512; i += 256)
            xs[i] = x[(long)(i >> 9) * K + k0 + (i & 511)];
        __syncthreads();
        if (jv) {
            int kb = s * 64;
            for (int kk = kb; kk < kb + 64; kk++) {
                float wv = w[(long)(k0 + kk) * N + j];
#pragma unroll
                for (int b = 0; b < 8; b++) acc[b] += xs[b * 512 + kk] * wv;
            }
        }
        __syncthreads();
    }
#pragma unroll
    for (int b = 0; b < 8; b++) red_[s][cj][b] = acc[b];
    __syncthreads();
    if (s == 0 && jv) {
#pragma unroll
        for (int b = 0; b < 8; b++) {
            float v = bias[j];
#pragma unroll
            for (int t = 0; t < 8; t++) v += red_[t][cj][b];
            y[(long)b * N + j] = do_relu ? fmaxf(v, 0.f) : v;
        }
    }
}

// ---------------------------------------------------------------------------
extern "C" void kernel_launch(void* const* d_in, const int* in_sizes, int n_in,
                              void* d_out, int out_size) {
    const float* feats    = (const float*)d_in[0];
    const float* w[6]     = {(const float*)d_in[1], (const float*)d_in[2],
                             (const float*)d_in[3], (const float*)d_in[4],
                             (const float*)d_in[5], (const float*)d_in[6]};
    const float* bn_gamma = (const float*)d_in[7];
    const float* bn_beta  = (const float*)d_in[8];
    const float* fc1_w = (const float*)d_in[9];
    const float* fc1_b = (const float*)d_in[10];
    const float* fc2_w = (const float*)d_in[11];
    const float* fc2_b = (const float*)d_in[12];
    const float* fc3_w = (const float*)d_in[13];
    const float* fc3_b = (const float*)d_in[14];
    const int* map1_in  = (const int*)d_in[15];
    const int* map1_out = (const int*)d_in[16];
    const int* map2_in  = (const int*)d_in[17];
    const int* map2_out = (const int*)d_in[18];
    const int* pool1_idx = (const int*)d_in[19];
    const int* pool2_idx = (const int*)d_in[20];
    const int* batch_idx = (const int*)d_in[21];

    int n1 = in_sizes[19];
    int n2 = in_sizes[20];
    int P1 = in_sizes[15] / 27;
    int P2 = in_sizes[17] / 27;

    float *acc, *glob, *fcb1, *fcb2;
    __half *hA, *hB, *wh;
    int *cnt1, *cnt2, *seg1, *ptr1, *inv1;
    cudaGetSymbolAddress((void**)&acc, g_acc);
    cudaGetSymbolAddress((void**)&hA, g_hA);
    cudaGetSymbolAddress((void**)&hB, g_hB);
    cudaGetSymbolAddress((void**)&wh, g_wh);
    cudaGetSymbolAddress((void**)&glob, g_glob);
    cudaGetSymbolAddress((void**)&fcb1, g_fcb1);
    cudaGetSymbolAddress((void**)&fcb2, g_fcb2);
    cudaGetSymbolAddress((void**)&cnt1, g_cnt1);
    cudaGetSymbolAddress((void**)&cnt2, g_cnt2);
    cudaGetSymbolAddress((void**)&seg1, g_seg1);
    cudaGetSymbolAddress((void**)&ptr1, g_ptr1);
    cudaGetSymbolAddress((void**)&inv1, g_inv1);

    static int smem_set = 0;
    if (!smem_set) {
        cudaFuncSetAttribute(k_conv_off,
                             cudaFuncAttributeMaxDynamicSharedMemorySize, SMEM_MAX);
        cudaFuncSetAttribute(k_conv_center,
                             cudaFuncAttributeMaxDynamicSharedMemorySize, SMEM_MAX);
        smem_set = 1;
    }

    long wofs[6];
    wofs[0] = 0;
    for (int l = 1; l < 6; l++)
        wofs[l] = wofs[l - 1] + (long)27 * 512 * (l == 1 ? 256 : 512);
    long wstride = (long)27 * 512 * 512;

    dim3 wtblk(32, 8);

    auto convC = [&](const __half* xin, const __half* Wc, int Kdim,
                     const int* m_in, const int* m_out, int* cnts, int P, int n) {
        int sm = SMEM_FOR(Kdim);
        k_conv_center<<<dim3(48, 4), 256, sm>>>(xin, Wc + (long)13 * 512 * Kdim,
                                                n, Kdim, acc);
        k_conv_off<<<dim3(2, 4, 26), 256, sm>>>(xin, Wc, m_in, m_out, cnts, P,
                                                Kdim, 1, acc);
    };
    auto bn_full = [&](int n, int layer, __half* hout) {
        k_bn_stats<<<(n + 127) / 128, 256>>>(acc, n, bn_gamma + layer * 512,
                                             bn_beta + layer * 512,
                                             1.0f / (float)n);
        int total8 = n * 64;
        int blocks = min((total8 + 255) / 256, 8192);
        k_bn_apply_h<<<blocks, 256>>>(acc, hout, total8);
    };
    auto bn_stats_only = [&](int n, int layer) {
        k_bn_stats<<<(n + 127) / 128, 256>>>(acc, n, bn_gamma + layer * 512,
                                             bn_beta + layer * 512,
                                             1.0f / (float)n);
    };

    // ---- prologue ----
    cudaMemsetAsync(cnt1, 0, 27 * 4);
    cudaMemsetAsync(cnt2, 0, 27 * 4);
    cudaMemsetAsync(seg1, 0, (n2 + 1) * 4);
    k_wt<<<dim3(16, 256 / 32, 27), wtblk>>>(w[0], wh + wofs[0], 256);
    k_f2h<<<4096, 256>>>(feats, hA, n1 * 256);
    k_count_par<<<dim3(27, 8), 256>>>(map1_out, P1, n1, cnt1);
    k_count_par<<<dim3(27, 8), 256>>>(map2_out, P2, n2, cnt2);

    // ---- conv1 ----
    convC(hA, wh + wofs[0], 256, map1_in, map1_out, cnt1, P1, n1);
    k_wt5<<<dim3(16, 16, 135), wtblk>>>(w[1], w[2], w[3], w[4], w[5],
                                        wh + wofs[1], wstride);
    k_hist<<<256, 256>>>(pool1_idx, n1, seg1);
    k_scan<<<1, 1024>>>(seg1, n2 + 1, ptr1);
    k_scatter<<<256, 256>>>(pool1_idx, n1, ptr1, inv1);
    bn_full(n1, 0, hB);

    convC(hB, wh + wofs[1], 512, map1_in, map1_out, cnt1, P1, n1); bn_full(n1, 1, hA);
    convC(hA, wh + wofs[2], 512, map1_in, map1_out, cnt1, P1, n1);
    bn_stats_only(n1, 2);

    // ---- pool1 with fused BN-apply ----
    k_pool_csr_bn<<<n2, 256>>>(acc, seg1, inv1, hA);

    // ---- level 2 ----
    convC(hA, wh + wofs[3], 512, map2_in, map2_out, cnt2, P2, n2); bn_full(n2, 3, hB);
    convC(hB, wh + wofs[4], 512, map2_in, map2_out, cnt2, P2, n2); bn_full(n2, 4, hA);
    convC(hA, wh + wofs[5], 512, map2_in, map2_out, cnt2, P2, n2);
    bn_stats_only(n2, 5);

    // ---- fused pool2 + global max with BN-apply ----
    cudaMemsetAsync(glob, 0, 8 * 512 * 4);
    k_pool_compose_bn<<<2048, 256>>>(acc, pool2_idx, batch_idx, glob, n2);

    // ---- FC head ----
    k_fc<<<128, 256>>>(glob, fc1_w, fc1_b, fcb1, 512, 4096, 1);
    k_fc<<<128, 256>>>(fcb1, fc2_w, fc2_b, fcb2, 4096, 4096, 1);
    k_fc<<<2, 256>>>(fcb2, fc3_w, fc3_b, (float*)d_out, 4096, 40, 0);
}